// round 1
// baseline (speedup 1.0000x reference)
#include <cuda_runtime.h>
#include <math.h>

// Problem constants
#define NN 4096          // nodes
#define BB 32            // batch
#define FF 66            // features (in_dim + units)
#define UU 64            // units
#define MM 5             // num matrices
#define FB 2112          // FF*BB columns of X
#define FB4 528          // FB/4
#define NNZ_MAX 128      // safe upper bound on nnz per row (binomial mean 41, std 6.4)

// ---------------- scratch (static device arrays; no allocations) ----------------
__device__ float g_X0[(size_t)NN * FB];        // gconv1 input, col = b*66+f
__device__ float g_X2[(size_t)NN * FB];        // gconv2 input (inputs + r*hx)
__device__ float g_M[4][(size_t)NN * FB];      // SpMM outputs m=1..4
__device__ float g_U[(size_t)BB * NN * UU];    // u gate, layout (B,N,U)
__device__ int   g_sidx[2][(size_t)NNZ_MAX * NN];  // ELL-T col indices
__device__ float g_sval[2][(size_t)NNZ_MAX * NN];  // ELL-T values
__device__ int   g_cnt[2][NN];                 // nnz per row

// ---------------- sparse structure build (one warp per row, coalesced) ----------
__global__ void build_sparse_k(const float* __restrict__ S, int sup) {
    int gw   = (blockIdx.x * blockDim.x + threadIdx.x) >> 5;  // row i
    int lane = threadIdx.x & 31;
    if (gw >= NN) return;
    const float* row = S + (size_t)gw * NN;
    int* idx = g_sidx[sup];
    float* val = g_sval[sup];
    int c = 0;
    for (int j0 = 0; j0 < NN; j0 += 32) {
        float v = row[j0 + lane];
        unsigned m = __ballot_sync(0xffffffffu, v != 0.0f);
        int pre = __popc(m & ((1u << lane) - 1u));
        if (v != 0.0f) {
            int slot = c + pre;
            if (slot < NNZ_MAX) {
                idx[(size_t)slot * NN + gw] = j0 + lane;
                val[(size_t)slot * NN + gw] = v;
            }
        }
        c += __popc(m);
    }
    if (lane == 0) g_cnt[sup][gw] = (c < NNZ_MAX) ? c : NNZ_MAX;
}

// ---------------- build X0 (and static part of X2) ------------------------------
__global__ void build_x_k(const float* __restrict__ inp, const float* __restrict__ hx) {
    int e = blockIdx.x * blockDim.x + threadIdx.x;
    if (e >= NN * FB) return;
    int n = e / FB;
    int rem = e - n * FB;
    int b = rem / FF;
    int f = rem - b * FF;
    float v;
    if (f < 2) {
        v = inp[(size_t)b * (NN * 2) + n * 2 + f];
        g_X2[e] = v;  // inputs part of gconv2 input is identical
    } else {
        v = hx[(size_t)b * (NN * UU) + (size_t)n * UU + (f - 2)];
    }
    g_X0[e] = v;
}

// ---------------- buffer selector -----------------------------------------------
__device__ __forceinline__ float* sel_buf(int s) {
    if (s == 0) return g_X0;
    if (s == 5) return g_X2;
    return g_M[s - 1];
}

// ---------------- SpMM: Y = alpha * S @ Xin  - (Xsub if sub_sel>=0) --------------
// Block = (one output row i, half of the 528 float4 columns). Gather X rows from L2.
__global__ __launch_bounds__(264) void spmm_k(int sup, int in_sel, int sub_sel,
                                              int out_sel, float alpha) {
    int i = blockIdx.y;
    int col = blockIdx.x * 264 + threadIdx.x;  // 0..527 (exact: 2*264 = 528)
    const float4* __restrict__ Xin = (const float4*)sel_buf(in_sel);
    const int*   __restrict__ sidx = g_sidx[sup];
    const float* __restrict__ sval = g_sval[sup];
    int cnt = g_cnt[sup][i];

    float4 acc = make_float4(0.f, 0.f, 0.f, 0.f);
    int k = 0;
    for (; k + 3 < cnt; k += 4) {
        int j0 = __ldg(&sidx[(size_t)(k + 0) * NN + i]);
        int j1 = __ldg(&sidx[(size_t)(k + 1) * NN + i]);
        int j2 = __ldg(&sidx[(size_t)(k + 2) * NN + i]);
        int j3 = __ldg(&sidx[(size_t)(k + 3) * NN + i]);
        float v0 = __ldg(&sval[(size_t)(k + 0) * NN + i]);
        float v1 = __ldg(&sval[(size_t)(k + 1) * NN + i]);
        float v2 = __ldg(&sval[(size_t)(k + 2) * NN + i]);
        float v3 = __ldg(&sval[(size_t)(k + 3) * NN + i]);
        float4 x0 = __ldg(&Xin[(size_t)j0 * FB4 + col]);
        float4 x1 = __ldg(&Xin[(size_t)j1 * FB4 + col]);
        float4 x2 = __ldg(&Xin[(size_t)j2 * FB4 + col]);
        float4 x3 = __ldg(&Xin[(size_t)j3 * FB4 + col]);
        acc.x = fmaf(v0, x0.x, acc.x); acc.y = fmaf(v0, x0.y, acc.y);
        acc.z = fmaf(v0, x0.z, acc.z); acc.w = fmaf(v0, x0.w, acc.w);
        acc.x = fmaf(v1, x1.x, acc.x); acc.y = fmaf(v1, x1.y, acc.y);
        acc.z = fmaf(v1, x1.z, acc.z); acc.w = fmaf(v1, x1.w, acc.w);
        acc.x = fmaf(v2, x2.x, acc.x); acc.y = fmaf(v2, x2.y, acc.y);
        acc.z = fmaf(v2, x2.z, acc.z); acc.w = fmaf(v2, x2.w, acc.w);
        acc.x = fmaf(v3, x3.x, acc.x); acc.y = fmaf(v3, x3.y, acc.y);
        acc.z = fmaf(v3, x3.z, acc.z); acc.w = fmaf(v3, x3.w, acc.w);
    }
    for (; k < cnt; k++) {
        int j  = __ldg(&sidx[(size_t)k * NN + i]);
        float v = __ldg(&sval[(size_t)k * NN + i]);
        float4 x = __ldg(&Xin[(size_t)j * FB4 + col]);
        acc.x = fmaf(v, x.x, acc.x); acc.y = fmaf(v, x.y, acc.y);
        acc.z = fmaf(v, x.z, acc.z); acc.w = fmaf(v, x.w, acc.w);
    }
    float4 r = make_float4(alpha * acc.x, alpha * acc.y, alpha * acc.z, alpha * acc.w);
    if (sub_sel >= 0) {
        const float4* Xs = (const float4*)sel_buf(sub_sel);
        float4 s = Xs[(size_t)i * FB4 + col];
        r.x -= s.x; r.y -= s.y; r.z -= s.z; r.w -= s.w;
    }
    ((float4*)sel_buf(out_sel))[(size_t)i * FB4 + col] = r;
}

// ---------------- projection 1: 131072 x 330 @ 330 x 128, sigmoid, gate split ----
// CTA: 64 rows (n-block) x 128 cols, fixed b. 256 threads, each 4 rows x 8 cols.
__global__ __launch_bounds__(256) void proj1_k(const float* __restrict__ W,
                                               const float* __restrict__ bias,
                                               const float* __restrict__ hx) {
    __shared__ float As[64][68];
    __shared__ float Ws[66][128];
    int b = blockIdx.y;
    int n0 = blockIdx.x * 64;
    int t = threadIdx.x;
    int tx = t & 15, ty = t >> 4;

    float acc[4][8];
#pragma unroll
    for (int rr = 0; rr < 4; rr++)
#pragma unroll
        for (int cc = 0; cc < 8; cc++) acc[rr][cc] = 0.f;

#pragma unroll 1
    for (int m = 0; m < MM; m++) {
        const float* Am = (m == 0) ? g_X0 : g_M[m - 1];
        for (int e = t; e < 64 * FF; e += 256) {
            int r = e / FF, f = e - r * FF;
            As[r][f] = Am[(size_t)(n0 + r) * FB + b * FF + f];
        }
        for (int e = t; e < FF * 128; e += 256) {
            int f = e >> 7, o = e & 127;
            Ws[f][o] = W[(size_t)(f * MM + m) * 128 + o];
        }
        __syncthreads();
#pragma unroll 6
        for (int kk = 0; kk < FF; kk++) {
            float a[4];
#pragma unroll
            for (int rr = 0; rr < 4; rr++) a[rr] = As[ty + 16 * rr][kk];
            float w[8];
#pragma unroll
            for (int cc = 0; cc < 8; cc++) w[cc] = Ws[kk][tx + 16 * cc];
#pragma unroll
            for (int rr = 0; rr < 4; rr++)
#pragma unroll
                for (int cc = 0; cc < 8; cc++)
                    acc[rr][cc] = fmaf(a[rr], w[cc], acc[rr][cc]);
        }
        __syncthreads();
    }

#pragma unroll
    for (int rr = 0; rr < 4; rr++) {
        int n = n0 + ty + 16 * rr;
#pragma unroll
        for (int cc = 0; cc < 8; cc++) {
            int o = tx + 16 * cc;
            float z = acc[rr][cc] + bias[o];
            float s = 1.0f / (1.0f + expf(-z));
            if (o < UU) {  // r gate -> write r*hx into gconv2 input features
                float h = hx[(size_t)b * (NN * UU) + (size_t)n * UU + o];
                g_X2[(size_t)n * FB + b * FF + 2 + o] = s * h;
            } else {       // u gate
                g_U[(size_t)b * (NN * UU) + (size_t)n * UU + (o - UU)] = s;
            }
        }
    }
}

// ---------------- projection 2: @ 330 x 64, tanh, final gate combine -------------
__global__ __launch_bounds__(256) void proj2_k(const float* __restrict__ W2,
                                               const float* __restrict__ b2,
                                               const float* __restrict__ hx,
                                               float* __restrict__ out) {
    __shared__ float As[64][68];
    __shared__ float Ws[66][64];
    int b = blockIdx.y;
    int n0 = blockIdx.x * 64;
    int t = threadIdx.x;
    int tx = t & 15, ty = t >> 4;

    float acc[4][4];
#pragma unroll
    for (int rr = 0; rr < 4; rr++)
#pragma unroll
        for (int cc = 0; cc < 4; cc++) acc[rr][cc] = 0.f;

#pragma unroll 1
    for (int m = 0; m < MM; m++) {
        const float* Am = (m == 0) ? g_X2 : g_M[m - 1];
        for (int e = t; e < 64 * FF; e += 256) {
            int r = e / FF, f = e - r * FF;
            As[r][f] = Am[(size_t)(n0 + r) * FB + b * FF + f];
        }
        for (int e = t; e < FF * 64; e += 256) {
            int f = e >> 6, o = e & 63;
            Ws[f][o] = W2[(size_t)(f * MM + m) * 64 + o];
        }
        __syncthreads();
#pragma unroll 6
        for (int kk = 0; kk < FF; kk++) {
            float a[4];
#pragma unroll
            for (int rr = 0; rr < 4; rr++) a[rr] = As[ty + 16 * rr][kk];
            float w[4];
#pragma unroll
            for (int cc = 0; cc < 4; cc++) w[cc] = Ws[kk][tx + 16 * cc];
#pragma unroll
            for (int rr = 0; rr < 4; rr++)
#pragma unroll
                for (int cc = 0; cc < 4; cc++)
                    acc[rr][cc] = fmaf(a[rr], w[cc], acc[rr][cc]);
        }
        __syncthreads();
    }

#pragma unroll
    for (int rr = 0; rr < 4; rr++) {
        int n = n0 + ty + 16 * rr;
#pragma unroll
        for (int cc = 0; cc < 4; cc++) {
            int o = tx + 16 * cc;
            float z = acc[rr][cc] + b2[o];
            float c = tanhf(z);
            size_t off = (size_t)b * (NN * UU) + (size_t)n * UU + o;
            float u = g_U[off];
            float h = hx[off];
            out[off] = u * h + (1.0f - u) * c;
        }
    }
}

// ---------------- launcher -------------------------------------------------------
extern "C" void kernel_launch(void* const* d_in, const int* in_sizes, int n_in,
                              void* d_out, int out_size) {
    const float* inputs = (const float*)d_in[0];
    const float* hx     = (const float*)d_in[1];
    const float* s0     = (const float*)d_in[2];
    const float* s1     = (const float*)d_in[3];
    const float* W      = (const float*)d_in[4];
    const float* bias   = (const float*)d_in[5];
    const float* W2     = (const float*)d_in[6];
    const float* b2     = (const float*)d_in[7];
    float* out = (float*)d_out;

    build_sparse_k<<<NN / 8, 256>>>(s0, 0);
    build_sparse_k<<<NN / 8, 256>>>(s1, 1);
    build_x_k<<<(NN * FB + 255) / 256, 256>>>(inputs, hx);

    dim3 sgrid(2, NN);
    // gconv1: mats m=1..4 in g_M[0..3]  (sel ids: 0=X0, 1..4=g_M[0..3], 5=X2)
    spmm_k<<<sgrid, 264>>>(0, 0, -1, 1, 1.0f);  // M0 = S0 @ X0
    spmm_k<<<sgrid, 264>>>(0, 1,  0, 2, 2.0f);  // M1 = 2*S0 @ M0 - X0
    spmm_k<<<sgrid, 264>>>(1, 0, -1, 3, 1.0f);  // M2 = S1 @ X0
    spmm_k<<<sgrid, 264>>>(1, 3,  0, 4, 2.0f);  // M3 = 2*S1 @ M2 - X0

    proj1_k<<<dim3(NN / 64, BB), 256>>>(W, bias, hx);  // writes g_X2 (r*hx) + g_U

    // gconv2 on X2
    spmm_k<<<sgrid, 264>>>(0, 5, -1, 1, 1.0f);
    spmm_k<<<sgrid, 264>>>(0, 1,  5, 2, 2.0f);
    spmm_k<<<sgrid, 264>>>(1, 5, -1, 3, 1.0f);
    spmm_k<<<sgrid, 264>>>(1, 3,  5, 4, 2.0f);

    proj2_k<<<dim3(NN / 64, BB), 256>>>(W2, b2, hx, out);
}